// round 8
// baseline (speedup 1.0000x reference)
#include <cuda_runtime.h>
#include <cuda_bf16.h>
#include <cstdint>

#define DEVINL __device__ __forceinline__

namespace {

constexpr int Hh = 16, Ss = 2048, Dd = 128;
constexpr int TM = 64;            // query tile
constexpr int TN = 64;            // key tile
constexpr int NKT = Ss / TN;      // 32
constexpr int NTHREADS = 128;     // 4 warps, 16 rows each
constexpr int ROWB = 272;         // 128 bf16 * 2B + 16B pad (conflict-free ldmatrix)
constexpr int TILE_B = 64 * ROWB;             // 17408 (64 rows x 128 cols bf16)
constexpr uint32_t SMEM_BYTES = 6 * TILE_B;   // 104448 -> 2 CTAs/SM

DEVINL uint32_t smem_u32(const void* p) {
  uint32_t a;
  asm("{ .reg .u64 t; cvta.to.shared.u64 t, %1; cvt.u32.u64 %0, t; }" : "=r"(a) : "l"(p));
  return a;
}

DEVINL uint32_t toff(int r, int c) { return (uint32_t)(r * ROWB + c * 2); }

// ---------------- fp32 -> bf16 hi/lo split ----------------
DEVINL void split2(float x, __nv_bfloat16& h, __nv_bfloat16& l) {
  h = __float2bfloat16(x);
  l = __float2bfloat16(x - __bfloat162float(h));
}
DEVINL uint32_t pack2(__nv_bfloat16 lo_el, __nv_bfloat16 hi_el) {
  return ((uint32_t)__bfloat16_as_ushort(hi_el) << 16) | (uint32_t)__bfloat16_as_ushort(lo_el);
}

// store 4 consecutive cols of one row into hi/lo tiles (8B chunks)
DEVINL void store_hl4(char* hB, char* lB, int row, int col, float4 val) {
  __nv_bfloat16 h0, h1, h2, h3, l0, l1, l2, l3;
  split2(val.x, h0, l0); split2(val.y, h1, l1);
  split2(val.z, h2, l2); split2(val.w, h3, l3);
  uint32_t off = toff(row, col);
  *reinterpret_cast<uint2*>(hB + off) = make_uint2(pack2(h0, h1), pack2(h2, h3));
  *reinterpret_cast<uint2*>(lB + off) = make_uint2(pack2(l0, l1), pack2(l2, l3));
}

// ---------------- MMA / ldmatrix wrappers ----------------
DEVINL void ldsm4(uint32_t* r, uint32_t addr) {
  asm volatile("ldmatrix.sync.aligned.m8n8.x4.shared.b16 {%0,%1,%2,%3}, [%4];"
               : "=r"(r[0]), "=r"(r[1]), "=r"(r[2]), "=r"(r[3]) : "r"(addr));
}
DEVINL void ldsm4t(uint32_t* r, uint32_t addr) {
  asm volatile("ldmatrix.sync.aligned.m8n8.x4.trans.shared.b16 {%0,%1,%2,%3}, [%4];"
               : "=r"(r[0]), "=r"(r[1]), "=r"(r[2]), "=r"(r[3]) : "r"(addr));
}
// non-volatile — pure register op; lets ptxas schedule/interleave HMMAs.
DEVINL void mma16816(float* c, const uint32_t* a, uint32_t b0, uint32_t b1) {
  asm("mma.sync.aligned.m16n8k16.row.col.f32.bf16.bf16.f32 "
      "{%0,%1,%2,%3}, {%4,%5,%6,%7}, {%8,%9}, {%0,%1,%2,%3};"
      : "+f"(c[0]), "+f"(c[1]), "+f"(c[2]), "+f"(c[3])
      : "r"(a[0]), "r"(a[1]), "r"(a[2]), "r"(a[3]), "r"(b0), "r"(b1));
}

__global__ void __launch_bounds__(NTHREADS, 2)
attn_mask_kernel(const float* __restrict__ q, const float* __restrict__ k,
                 const float* __restrict__ v, const float* __restrict__ mask,
                 float* __restrict__ out) {
  extern __shared__ char smem[];
  const uint32_t sb = smem_u32(smem);
  const int tid = threadIdx.x, wid = tid >> 5, lane = tid & 31;
  const int bh = (int)blockIdx.z * Hh + (int)blockIdx.y;
  const int s0 = (int)blockIdx.x * TM;

  char* QH = smem;
  char* QL = smem + TILE_B;
  char* KH = smem + 2 * TILE_B;
  char* KL = smem + 3 * TILE_B;
  char* VH = smem + 4 * TILE_B;
  char* VL = smem + 5 * TILE_B;

  // ---- load + split Q tile (once): 64 rows x 128 cols = 2048 float4 ----
  {
    const float4* qsrc = (const float4*)(q + ((size_t)bh * Ss + s0) * Dd);
#pragma unroll
    for (int i = 0; i < 16; ++i) {
      int f = tid + i * NTHREADS;
      float4 val = qsrc[f];
      int e = f * 4;
      store_hl4(QH, QL, e >> 7, e & 127, val);
    }
  }

  // accumulators: S [8 n-frags][4] over TN=64, O [16 n-frags][4] over Dd=128
  float S[8][4];
  float O[16][4];
#pragma unroll
  for (int i = 0; i < 16; ++i) { O[i][0] = O[i][1] = O[i][2] = O[i][3] = 0.f; }

  const int wrow0 = wid * 16;
  const int lrow = lane & 7;
  const int lq = (lane >> 3) & 1;
  const int lh = lane >> 4;

  // ldmatrix lane base addresses
  const uint32_t qA_h = sb + 0 * TILE_B + toff(wrow0 + lrow + lq * 8, lh * 8);
  const uint32_t qA_l = qA_h + TILE_B;
  const uint32_t kB_h = sb + 2 * TILE_B + toff(lrow + lh * 8, lq * 8);
  const uint32_t kB_l = kB_h + TILE_B;
  const uint32_t vB_h = sb + 4 * TILE_B + toff(lrow + lq * 8, lh * 8);
  const uint32_t vB_l = vB_h + TILE_B;

  const int mr = wrow0 + (lane >> 2);      // this thread's row (and +8)
  const int mc = (lane & 3) * 2;           // col offset within an 8-wide n-frag
  const float* mbase = mask + ((size_t)bh * Ss + (s0 + mr)) * Ss;

  const float4* kbh = (const float4*)(k + (size_t)bh * Ss * Dd);
  const float4* vbh = (const float4*)(v + (size_t)bh * Ss * Dd);
  constexpr int F4_PER_TILE = TN * Dd / 4;  // 2048 float4 per 64-row tile

  // ---- prologue: prefetch first half of tile 0 K/V into registers ----
  float4 kr[8], vr[8];
#pragma unroll
  for (int i = 0; i < 8; ++i) {
    kr[i] = kbh[tid + i * NTHREADS];
    vr[i] = vbh[tid + i * NTHREADS];
  }

#pragma unroll 1
  for (int kt = 0; kt < NKT; ++kt) {
    const int t0 = kt * TN;
    const int tnext = (kt + 1 < NKT) ? (kt + 1) : 0;
    const float4* kcur = kbh + (size_t)kt * F4_PER_TILE;
    const float4* vcur = vbh + (size_t)kt * F4_PER_TILE;
    const float4* knext = kbh + (size_t)tnext * F4_PER_TILE;
    const float4* vnext = vbh + (size_t)tnext * F4_PER_TILE;

    __syncthreads();  // prior iteration's K/V smem reads complete

    // ---- store prefetched K/V regs -> smem (split hi/lo) ----
#pragma unroll
    for (int i = 0; i < 8; ++i) {
      int f = tid + i * NTHREADS;
      int e = f * 4;
      int row = e >> 7, col = e & 127;
      store_hl4(KH, KL, row, col, kr[i]);
      store_hl4(VH, VL, row, col, vr[i]);
    }
    // second half of the tile: direct load + store
#pragma unroll
    for (int i = 0; i < 8; ++i) {
      int f = tid + (i + 8) * NTHREADS;
      float4 kv = kcur[f];
      float4 vv = vcur[f];
      int e = f * 4;
      int row = e >> 7, col = e & 127;
      store_hl4(KH, KL, row, col, kv);
      store_hl4(VH, VL, row, col, vv);
    }
    __syncthreads();

    // ---- GEMM1: S[16x64] = Q @ K^T (3-term bf16 split, interleaved acc) ----
#pragma unroll
    for (int i = 0; i < 8; ++i) { S[i][0] = S[i][1] = S[i][2] = S[i][3] = 0.f; }
#pragma unroll
    for (int kk = 0; kk < 8; ++kk) {
      uint32_t ah[4], al[4];
      ldsm4(ah, qA_h + kk * 32);
      ldsm4(al, qA_l + kk * 32);
#pragma unroll
      for (int ntp = 0; ntp < 4; ++ntp) {
        uint32_t bh_[4], bl_[4];
        ldsm4(bh_, kB_h + (uint32_t)(ntp * 16 * ROWB) + kk * 32);
        ldsm4(bl_, kB_l + (uint32_t)(ntp * 16 * ROWB) + kk * 32);
        mma16816(S[2 * ntp],     ah, bh_[0], bh_[1]);
        mma16816(S[2 * ntp + 1], ah, bh_[2], bh_[3]);
        mma16816(S[2 * ntp],     ah, bl_[0], bl_[1]);
        mma16816(S[2 * ntp + 1], ah, bl_[2], bl_[3]);
        mma16816(S[2 * ntp],     al, bh_[0], bh_[1]);
        mma16816(S[2 * ntp + 1], al, bh_[2], bh_[3]);
      }
    }

    // ---- P = S * mask (streamed directly from gmem) ----
#pragma unroll
    for (int nf = 0; nf < 8; ++nf) {
      const float* mp = mbase + t0 + nf * 8 + mc;
      float2 m0 = __ldcs((const float2*)mp);
      float2 m1 = __ldcs((const float2*)(mp + 8 * Ss));
      S[nf][0] *= m0.x; S[nf][1] *= m0.y;
      S[nf][2] *= m1.x; S[nf][3] *= m1.y;
    }

    // ---- GEMM2: O += P @ V, next-tile K/V prefetch folded in (4 kk steps) ----
#pragma unroll
    for (int kk = 0; kk < 4; ++kk) {
      // build P A-fragments for this k-step from S n-frags 2kk, 2kk+1
      uint32_t ph[4], pl[4];
      {
        __nv_bfloat16 h0, h1, h2, h3, l0, l1, l2, l3;
        split2(S[2 * kk][0], h0, l0); split2(S[2 * kk][1], h1, l1);
        split2(S[2 * kk][2], h2, l2); split2(S[2 * kk][3], h3, l3);
        ph[0] = pack2(h0, h1); ph[1] = pack2(h2, h3);
        pl[0] = pack2(l0, l1); pl[1] = pack2(l2, l3);
        split2(S[2 * kk + 1][0], h0, l0); split2(S[2 * kk + 1][1], h1, l1);
        split2(S[2 * kk + 1][2], h2, l2); split2(S[2 * kk + 1][3], h3, l3);
        ph[2] = pack2(h0, h1); ph[3] = pack2(h2, h3);
        pl[2] = pack2(l0, l1); pl[3] = pack2(l2, l3);
      }
      // prefetch two K and two V float4 of the next tile (S[2kk..2kk+1] died)
      kr[2 * kk] = knext[tid + (2 * kk) * NTHREADS];
      kr[2 * kk + 1] = knext[tid + (2 * kk + 1) * NTHREADS];
      vr[2 * kk] = vnext[tid + (2 * kk) * NTHREADS];
      vr[2 * kk + 1] = vnext[tid + (2 * kk + 1) * NTHREADS];
#pragma unroll
      for (int np = 0; np < 8; ++np) {
        uint32_t bh_[4], bl_[4];
        ldsm4t(bh_, vB_h + (uint32_t)(kk * 16 * ROWB) + np * 32);
        ldsm4t(bl_, vB_l + (uint32_t)(kk * 16 * ROWB) + np * 32);
        mma16816(O[2 * np],     ph, bh_[0], bh_[1]);
        mma16816(O[2 * np + 1], ph, bh_[2], bh_[3]);
        mma16816(O[2 * np],     ph, bl_[0], bl_[1]);
        mma16816(O[2 * np + 1], ph, bl_[2], bl_[3]);
        mma16816(O[2 * np],     pl, bh_[0], bh_[1]);
        mma16816(O[2 * np + 1], pl, bh_[2], bh_[3]);
      }
    }
  }

  // ---- epilogue: O regs -> gmem ----
  {
    float* ob = out + ((size_t)bh * Ss + (s0 + mr)) * Dd + mc;
#pragma unroll
    for (int nf = 0; nf < 16; ++nf) {
      *(float2*)(ob + nf * 8) = make_float2(O[nf][0], O[nf][1]);
      *(float2*)(ob + 8 * Dd + nf * 8) = make_float2(O[nf][2], O[nf][3]);
    }
  }
}

}  // namespace

extern "C" void kernel_launch(void* const* d_in, const int* in_sizes, int n_in,
                              void* d_out, int out_size) {
  (void)in_sizes; (void)n_in; (void)out_size;
  const float* q = (const float*)d_in[0];
  const float* k = (const float*)d_in[1];
  const float* v = (const float*)d_in[2];
  const float* m = (const float*)d_in[3];
  float* out = (float*)d_out;

  cudaFuncSetAttribute(attn_mask_kernel, cudaFuncAttributeMaxDynamicSharedMemorySize,
                       SMEM_BYTES);
  dim3 grid(Ss / TM, Hh, 2);
  attn_mask_kernel<<<grid, NTHREADS, SMEM_BYTES>>>(q, k, v, m, out);
}

// round 9
// speedup vs baseline: 1.1547x; 1.1547x over previous
#include <cuda_runtime.h>
#include <cuda_bf16.h>
#include <cstdint>

#define DEVINL __device__ __forceinline__

namespace {

constexpr int Hh = 16, Ss = 2048, Dd = 128;
constexpr int TM = 128;           // query tile
constexpr int TN = 128;           // key tile
constexpr int NKT = Ss / TN;      // 16
constexpr int NTHREADS = 256;     // 8 warps, 16 rows each
constexpr int ROWB = 272;         // 128 bf16 * 2B + 16B pad (conflict-free ldmatrix)
constexpr int TILE_B = 128 * ROWB;            // 34816
constexpr uint32_t SMEM_BYTES = 6 * TILE_B;   // 208896 (QH QL KH KL VH VL)

DEVINL uint32_t smem_u32(const void* p) {
  uint32_t a;
  asm("{ .reg .u64 t; cvta.to.shared.u64 t, %1; cvt.u32.u64 %0, t; }" : "=r"(a) : "l"(p));
  return a;
}

DEVINL uint32_t toff(int r, int c) { return (uint32_t)(r * ROWB + c * 2); }

// ---------------- fp32 -> bf16 hi/lo split ----------------
DEVINL void split2(float x, __nv_bfloat16& h, __nv_bfloat16& l) {
  h = __float2bfloat16(x);
  l = __float2bfloat16(x - __bfloat162float(h));
}
DEVINL uint32_t pack2(__nv_bfloat16 lo_el, __nv_bfloat16 hi_el) {
  return ((uint32_t)__bfloat16_as_ushort(hi_el) << 16) | (uint32_t)__bfloat16_as_ushort(lo_el);
}

// store 4 consecutive cols of one row into hi/lo tiles (8B chunks)
DEVINL void store_hl4(char* hB, char* lB, int row, int col, float4 val) {
  __nv_bfloat16 h0, h1, h2, h3, l0, l1, l2, l3;
  split2(val.x, h0, l0); split2(val.y, h1, l1);
  split2(val.z, h2, l2); split2(val.w, h3, l3);
  uint32_t off = toff(row, col);
  *reinterpret_cast<uint2*>(hB + off) = make_uint2(pack2(h0, h1), pack2(h2, h3));
  *reinterpret_cast<uint2*>(lB + off) = make_uint2(pack2(l0, l1), pack2(l2, l3));
}

// ---------------- MMA / ldmatrix wrappers ----------------
DEVINL void ldsm4(uint32_t* r, uint32_t addr) {
  asm volatile("ldmatrix.sync.aligned.m8n8.x4.shared.b16 {%0,%1,%2,%3}, [%4];"
               : "=r"(r[0]), "=r"(r[1]), "=r"(r[2]), "=r"(r[3]) : "r"(addr));
}
DEVINL void ldsm4t(uint32_t* r, uint32_t addr) {
  asm volatile("ldmatrix.sync.aligned.m8n8.x4.trans.shared.b16 {%0,%1,%2,%3}, [%4];"
               : "=r"(r[0]), "=r"(r[1]), "=r"(r[2]), "=r"(r[3]) : "r"(addr));
}
// non-volatile — pure register op; lets ptxas schedule/interleave HMMAs.
DEVINL void mma16816(float* c, const uint32_t* a, uint32_t b0, uint32_t b1) {
  asm("mma.sync.aligned.m16n8k16.row.col.f32.bf16.bf16.f32 "
      "{%0,%1,%2,%3}, {%4,%5,%6,%7}, {%8,%9}, {%0,%1,%2,%3};"
      : "+f"(c[0]), "+f"(c[1]), "+f"(c[2]), "+f"(c[3])
      : "r"(a[0]), "r"(a[1]), "r"(a[2]), "r"(a[3]), "r"(b0), "r"(b1));
}

__global__ void __launch_bounds__(NTHREADS, 1)
attn_mask_kernel(const float* __restrict__ q, const float* __restrict__ k,
                 const float* __restrict__ v, const float* __restrict__ mask,
                 float* __restrict__ out) {
  extern __shared__ char smem[];
  const uint32_t sb = smem_u32(smem);
  const int tid = threadIdx.x, wid = tid >> 5, lane = tid & 31;
  const int bh = (int)blockIdx.z * Hh + (int)blockIdx.y;
  const int s0 = (int)blockIdx.x * TM;

  char* QH = smem;
  char* QL = smem + TILE_B;
  char* KH = smem + 2 * TILE_B;
  char* KL = smem + 3 * TILE_B;
  char* VH = smem + 4 * TILE_B;
  char* VL = smem + 5 * TILE_B;

  // ---- load + split Q tile (once) ----
  {
    const float4* qsrc = (const float4*)(q + ((size_t)bh * Ss + s0) * Dd);
#pragma unroll
    for (int i = 0; i < 16; ++i) {
      int f = tid + i * NTHREADS;
      float4 val = qsrc[f];
      int e = f * 4;
      store_hl4(QH, QL, e >> 7, e & 127, val);
    }
  }

  // accumulators: S/P [16 n-frags][4], O [16 n-frags][4]
  float S[16][4];
  float O[16][4];
#pragma unroll
  for (int i = 0; i < 16; ++i) { O[i][0] = O[i][1] = O[i][2] = O[i][3] = 0.f; }

  const int wrow0 = wid * 16;
  const int lrow = lane & 7;
  const int lq = (lane >> 3) & 1;
  const int lh = lane >> 4;

  // ldmatrix lane base addresses
  const uint32_t qA_h = sb + 0 * TILE_B + toff(wrow0 + lrow + lq * 8, lh * 8);
  const uint32_t qA_l = qA_h + TILE_B;
  const uint32_t kB_h = sb + 2 * TILE_B + toff(lrow + lh * 8, lq * 8);
  const uint32_t kB_l = kB_h + TILE_B;
  const uint32_t vB_h = sb + 4 * TILE_B + toff(lrow + lq * 8, lh * 8);
  const uint32_t vB_l = vB_h + TILE_B;

  const int mr = wrow0 + (lane >> 2);      // this thread's row (and +8)
  const int mc = (lane & 3) * 2;           // col offset within an 8-wide n-frag
  const float* mbase = mask + ((size_t)bh * Ss + (s0 + mr)) * Ss;

  const float4* kbh = (const float4*)(k + (size_t)bh * Ss * Dd);
  const float4* vbh = (const float4*)(v + (size_t)bh * Ss * Dd);
  constexpr int F4_PER_TILE = TN * Dd / 4;  // 4096 float4 per tile

  // ---- prologue: prefetch tile 0 K/V into registers ----
  float4 kr[8], vr[8];
#pragma unroll
  for (int i = 0; i < 8; ++i) {
    kr[i] = kbh[tid + i * NTHREADS];
    vr[i] = vbh[tid + i * NTHREADS];
  }

#pragma unroll 1
  for (int kt = 0; kt < NKT; ++kt) {
    const int t0 = kt * TN;
    const int tnext = (kt + 1 < NKT) ? (kt + 1) : 0;
    const float4* knext = kbh + (size_t)tnext * F4_PER_TILE;
    const float4* vnext = vbh + (size_t)tnext * F4_PER_TILE;

    __syncthreads();  // prior iteration's K/V smem reads complete

    // ---- store prefetched K/V regs -> smem (split hi/lo) ----
#pragma unroll
    for (int i = 0; i < 8; ++i) {
      int f = tid + i * NTHREADS;
      int e = f * 4;
      int row = e >> 7, col = e & 127;
      store_hl4(KH, KL, row, col, kr[i]);
      store_hl4(VH, VL, row, col, vr[i]);
    }
    {
      // second half of the tile (rows 64-127)
#pragma unroll
      for (int i = 0; i < 8; ++i) {
        int f = tid + (i + 8) * NTHREADS;
        float4 kv = kbh[(size_t)kt * F4_PER_TILE + f];
        float4 vv = vbh[(size_t)kt * F4_PER_TILE + f];
        int e = f * 4;
        int row = e >> 7, col = e & 127;
        store_hl4(KH, KL, row, col, kv);
        store_hl4(VH, VL, row, col, vv);
      }
    }

    // ---- mask pipeline prologue: buffers for GEMM2 kk=0,1
    //      (latency hidden under the STS block above / barrier below) ----
    float2 mb[2][4];
#pragma unroll
    for (int s = 0; s < 2; ++s) {
      const float* mp0 = mbase + t0 + (2 * s) * 8 + mc;
      const float* mp1 = mbase + t0 + (2 * s + 1) * 8 + mc;
      mb[s][0] = __ldcs((const float2*)mp0);
      mb[s][1] = __ldcs((const float2*)(mp0 + 8 * Ss));
      mb[s][2] = __ldcs((const float2*)mp1);
      mb[s][3] = __ldcs((const float2*)(mp1 + 8 * Ss));
    }

    __syncthreads();

    // ---- GEMM1: S = Q @ K^T (3-term bf16 split, interleaved accumulators) ----
#pragma unroll
    for (int i = 0; i < 16; ++i) { S[i][0] = S[i][1] = S[i][2] = S[i][3] = 0.f; }
#pragma unroll
    for (int kk = 0; kk < 8; ++kk) {
      uint32_t ah[4], al[4];
      ldsm4(ah, qA_h + kk * 32);
      ldsm4(al, qA_l + kk * 32);
#pragma unroll
      for (int ntp = 0; ntp < 8; ++ntp) {
        uint32_t bh_[4], bl_[4];
        ldsm4(bh_, kB_h + (uint32_t)(ntp * 16 * ROWB) + kk * 32);
        ldsm4(bl_, kB_l + (uint32_t)(ntp * 16 * ROWB) + kk * 32);
        mma16816(S[2 * ntp],     ah, bh_[0], bh_[1]);
        mma16816(S[2 * ntp + 1], ah, bh_[2], bh_[3]);
        mma16816(S[2 * ntp],     ah, bl_[0], bl_[1]);
        mma16816(S[2 * ntp + 1], ah, bl_[2], bl_[3]);
        mma16816(S[2 * ntp],     al, bh_[0], bh_[1]);
        mma16816(S[2 * ntp + 1], al, bh_[2], bh_[3]);
      }
    }

    // ---- GEMM2: O += (S*mask) @ V; mask applied per kk from pipelined bufs ----
#pragma unroll
    for (int kk = 0; kk < 8; ++kk) {
      // apply mask buffer (loaded >=2 steps ago) to S[2kk], S[2kk+1]
      {
        const float2* m = mb[kk & 1];
        S[2 * kk][0] *= m[0].x;     S[2 * kk][1] *= m[0].y;
        S[2 * kk][2] *= m[1].x;     S[2 * kk][3] *= m[1].y;
        S[2 * kk + 1][0] *= m[2].x; S[2 * kk + 1][1] *= m[2].y;
        S[2 * kk + 1][2] *= m[3].x; S[2 * kk + 1][3] *= m[3].y;
      }
      // refill this buffer for step kk+2 (latency hidden under the MMA block)
      if (kk + 2 < 8) {
        const int nf0 = 2 * (kk + 2), nf1 = nf0 + 1;
        const float* mp0 = mbase + t0 + nf0 * 8 + mc;
        const float* mp1 = mbase + t0 + nf1 * 8 + mc;
        mb[kk & 1][0] = __ldcs((const float2*)mp0);
        mb[kk & 1][1] = __ldcs((const float2*)(mp0 + 8 * Ss));
        mb[kk & 1][2] = __ldcs((const float2*)mp1);
        mb[kk & 1][3] = __ldcs((const float2*)(mp1 + 8 * Ss));
      }
      // build P A-fragments for this k-step from S n-frags 2kk, 2kk+1
      uint32_t ph[4], pl[4];
      {
        __nv_bfloat16 h0, h1, h2, h3, l0, l1, l2, l3;
        split2(S[2 * kk][0], h0, l0); split2(S[2 * kk][1], h1, l1);
        split2(S[2 * kk][2], h2, l2); split2(S[2 * kk][3], h3, l3);
        ph[0] = pack2(h0, h1); ph[1] = pack2(h2, h3);
        pl[0] = pack2(l0, l1); pl[1] = pack2(l2, l3);
        split2(S[2 * kk + 1][0], h0, l0); split2(S[2 * kk + 1][1], h1, l1);
        split2(S[2 * kk + 1][2], h2, l2); split2(S[2 * kk + 1][3], h3, l3);
        ph[2] = pack2(h0, h1); ph[3] = pack2(h2, h3);
        pl[2] = pack2(l0, l1); pl[3] = pack2(l2, l3);
      }
      // prefetch one K and one V float4 of the next tile (S[2kk..2kk+1] died)
      kr[kk] = knext[tid + kk * NTHREADS];
      vr[kk] = vnext[tid + kk * NTHREADS];
#pragma unroll
      for (int np = 0; np < 8; ++np) {
        uint32_t bh_[4], bl_[4];
        ldsm4t(bh_, vB_h + (uint32_t)(kk * 16 * ROWB) + np * 32);
        ldsm4t(bl_, vB_l + (uint32_t)(kk * 16 * ROWB) + np * 32);
        mma16816(O[2 * np],     ph, bh_[0], bh_[1]);
        mma16816(O[2 * np + 1], ph, bh_[2], bh_[3]);
        mma16816(O[2 * np],     ph, bl_[0], bl_[1]);
        mma16816(O[2 * np + 1], ph, bl_[2], bl_[3]);
        mma16816(O[2 * np],     pl, bh_[0], bh_[1]);
        mma16816(O[2 * np + 1], pl, bh_[2], bh_[3]);
      }
    }
  }

  // ---- epilogue: O regs -> gmem ----
  {
    float* ob = out + ((size_t)bh * Ss + (s0 + mr)) * Dd + mc;
#pragma unroll
    for (int nf = 0; nf < 16; ++nf) {
      *(float2*)(ob + nf * 8) = make_float2(O[nf][0], O[nf][1]);
      *(float2*)(ob + 8 * Dd + nf * 8) = make_float2(O[nf][2], O[nf][3]);
    }
  }
}

}  // namespace

extern "C" void kernel_launch(void* const* d_in, const int* in_sizes, int n_in,
                              void* d_out, int out_size) {
  (void)in_sizes; (void)n_in; (void)out_size;
  const float* q = (const float*)d_in[0];
  const float* k = (const float*)d_in[1];
  const float* v = (const float*)d_in[2];
  const float* m = (const float*)d_in[3];
  float* out = (float*)d_out;

  cudaFuncSetAttribute(attn_mask_kernel, cudaFuncAttributeMaxDynamicSharedMemorySize,
                       SMEM_BYTES);
  dim3 grid(Ss / TM, Hh, 2);
  attn_mask_kernel<<<grid, NTHREADS, SMEM_BYTES>>>(q, k, v, m, out);
}